// round 4
// baseline (speedup 1.0000x reference)
#include <cuda_runtime.h>
#include <cuda_bf16.h>
#include <cstdint>

#define BB 32
#define NN 64
#define FF 1280
#define HH 512
#define EE 512
#define VV 10000
#define TT 80
#define G4 2048

#define OFF_H   25600000ll
#define OFF_C   25616384ll
#define OFF_ATT 25632768ll

// ---------------- device state ----------------
__device__ float g_h[2][BB * HH];
__device__ float g_c[2][BB * HH];
__device__ float g_hq[BB * HH];
__device__ float g_gate[BB * FF];
__device__ float g_ctxg[BB * FF];
__device__ float g_scor[BB * NN];
__device__ float g_encproj[BB * NN * HH];
__device__ float g_gpart[6][BB * G4];
__device__ unsigned long long g_amax[BB];

// ---------------- helpers ----------------
__device__ __forceinline__ unsigned long long pk2(float lo, float hi) {
    unsigned long long r;
    asm("mov.b64 %0, {%1,%2};" : "=l"(r) : "f"(lo), "f"(hi));
    return r;
}
__device__ __forceinline__ void upk2(unsigned long long v, float& lo, float& hi) {
    asm("mov.b64 {%0,%1}, %2;" : "=f"(lo), "=f"(hi) : "l"(v));
}
__device__ __forceinline__ void fma2(unsigned long long& d, unsigned long long a,
                                     unsigned long long b) {
    asm("fma.rn.f32x2 %0, %1, %2, %0;" : "+l"(d) : "l"(a), "l"(b));
}
__device__ __forceinline__ float sigf(float x) { return 1.0f / (1.0f + expf(-x)); }
__device__ __forceinline__ unsigned mono32(float f) {
    unsigned u = __float_as_uint(f);
    return (u & 0x80000000u) ? ~u : (u | 0x80000000u);
}

// ---------------- GEMM v4 ----------------
// C[32, 64-col tile] = A[32,K] @ W[K,N].  512 threads (16 warps).
// warp rp -> rows (2rp, 2rp+1); lane -> cols (col0, col0+1).
// A staged ONCE into dynamic smem, row-pair interleaved:
//   s[rp*2K + k*2 + (row&1)]  -> LDS.128 gives (k,k+1) x (row0,row1).
// W streamed with a double-buffered 8-deep prefetch pipeline (16 LDG in flight).
template <class AElem>
__device__ __forceinline__ void gemm_v4(AElem aelem, const float* __restrict__ W,
    int ldw, int K, int N, int bcol, unsigned long long acc[2], float* s)
{
    const int tid = threadIdx.x;
    const int lane = tid & 31;
    const int rp = tid >> 5;
    const int col0 = bcol + lane * 2;
    const int K2 = 2 * K;

    for (int idx = tid; idx < 32 * K; idx += 512) {
        int row = idx / K;
        int k = idx - row * K;
        s[(row >> 1) * K2 + k * 2 + (row & 1)] = aelem(row, k);
    }
    __syncthreads();
    const float* sa = s + rp * K2;

    if (col0 + 2 <= N) {
        const float* Wp = W + col0;
        float2 wa[8], wb[8];
#pragma unroll
        for (int u = 0; u < 8; u++) wa[u] = *(const float2*)(Wp + (size_t)u * ldw);
        for (int k0 = 0; k0 < K; k0 += 16) {
#pragma unroll
            for (int u = 0; u < 8; u++)
                wb[u] = *(const float2*)(Wp + (size_t)(k0 + 8 + u) * ldw);
#pragma unroll
            for (int u = 0; u < 4; u++) {
                float4 a4 = *(const float4*)(sa + (k0 + 2 * u) * 2);
                unsigned long long w0 = pk2(wa[2 * u].x, wa[2 * u].y);
                fma2(acc[0], w0, pk2(a4.x, a4.x));
                fma2(acc[1], w0, pk2(a4.y, a4.y));
                unsigned long long w1 = pk2(wa[2 * u + 1].x, wa[2 * u + 1].y);
                fma2(acc[0], w1, pk2(a4.z, a4.z));
                fma2(acc[1], w1, pk2(a4.w, a4.w));
            }
            if (k0 + 16 < K) {
#pragma unroll
                for (int u = 0; u < 8; u++)
                    wa[u] = *(const float2*)(Wp + (size_t)(k0 + 16 + u) * ldw);
            }
#pragma unroll
            for (int u = 0; u < 4; u++) {
                float4 a4 = *(const float4*)(sa + (k0 + 8 + 2 * u) * 2);
                unsigned long long w0 = pk2(wb[2 * u].x, wb[2 * u].y);
                fma2(acc[0], w0, pk2(a4.x, a4.x));
                fma2(acc[1], w0, pk2(a4.y, a4.y));
                unsigned long long w1 = pk2(wb[2 * u + 1].x, wb[2 * u + 1].y);
                fma2(acc[0], w1, pk2(a4.z, a4.z));
                fma2(acc[1], w1, pk2(a4.w, a4.w));
            }
        }
    } else {
#pragma unroll 4
        for (int k = 0; k < K; k++) {
            float2 aa = *(const float2*)(sa + k * 2);
            const float* wr = W + (size_t)k * ldw;
            float wx = (col0 + 0 < N) ? wr[col0] : 0.f;
            float wy = (col0 + 1 < N) ? wr[col0 + 1] : 0.f;
            unsigned long long w01 = pk2(wx, wy);
            fma2(acc[0], w01, pk2(aa.x, aa.x));
            fma2(acc[1], w01, pk2(aa.y, aa.y));
        }
    }
}

// Epilogue: +bias, optional sigmoid, store (with N guard).
__device__ __forceinline__ void store_tile(unsigned long long acc[2],
    float* C, int ldc, int bcol, int N, const float* __restrict__ bias, int act)
{
    int lane = threadIdx.x & 31, rp = threadIdx.x >> 5;
    int col0 = bcol + lane * 2;
    float v0, v1, u0, u1;
    upk2(acc[0], v0, v1);   // row 2rp, cols col0/col0+1
    upk2(acc[1], u0, u1);   // row 2rp+1
#pragma unroll
    for (int q = 0; q < 2; q++) {
        int cc = col0 + q;
        if (cc >= N) continue;
        float a = (q == 0) ? v0 : v1;
        float b = (q == 0) ? u0 : u1;
        float bb = bias ? bias[cc] : 0.f;
        a += bb; b += bb;
        if (act == 1) { a = sigf(a); b = sigf(b); }
        C[(size_t)(2 * rp) * ldc + cc] = a;
        C[(size_t)(2 * rp + 1) * ldc + cc] = b;
    }
}

// ---------------- setup ----------------
__global__ void __launch_bounds__(512) k_encproj(const float* __restrict__ feat,
                                                 const float* __restrict__ W2,
                                                 const float* __restrict__ b2)
{
    extern __shared__ float s_dyn[];
    unsigned long long acc[2] = {0, 0};
    int bcol = blockIdx.x * 64;
    const float* A = feat + (size_t)blockIdx.y * 32 * FF;
    gemm_v4([&](int r, int k) { return A[(size_t)r * FF + k]; },
            W2, HH, FF, HH, bcol, acc, s_dyn);
    store_tile(acc, g_encproj + (size_t)blockIdx.y * 32 * HH, HH, bcol, HH, b2, 0);
}

__global__ void __launch_bounds__(256) k_init(const float* __restrict__ feat,
                                              const float* __restrict__ Wh,
                                              const float* __restrict__ bh,
                                              const float* __restrict__ Wc,
                                              const float* __restrict__ bc)
{
    __shared__ float s_mean[FF];
    int b = blockIdx.x, tid = threadIdx.x;
    const float* fb = feat + (size_t)b * NN * FF;
    for (int f = tid; f < FF; f += 256) {
        float s = 0.f;
#pragma unroll 8
        for (int n = 0; n < NN; n++) s += fb[(size_t)n * FF + f];
        s_mean[f] = s * (1.0f / NN);
    }
    __syncthreads();
    for (int j = tid; j < HH; j += 256) {
        float ha = bh[j], ca = bc[j];
#pragma unroll 8
        for (int f = 0; f < FF; f++) {
            float m = s_mean[f];
            ha = fmaf(m, Wh[(size_t)f * HH + j], ha);
            ca = fmaf(m, Wc[(size_t)f * HH + j], ca);
        }
        g_h[0][b * HH + j] = ha;
        g_c[0][b * HH + j] = ca;
    }
    if (tid == 0) g_amax[b] = (unsigned long long)(0xFFFFFFFFu - 1u);  // SOS=1
}

// ---------------- per-step ----------------
// K_G1: hq = h@W1+b1 ; gate = sig(h@Wg+bg) ; gpart0 = emb[tok]@WxTop+blstm ; gpart1 = h@Whh
__global__ void __launch_bounds__(512) k_g1(int p, const float* __restrict__ emb,
    const float* __restrict__ W1, const float* __restrict__ b1,
    const float* __restrict__ Wg, const float* __restrict__ bg,
    const float* __restrict__ Wx, const float* __restrict__ Whh,
    const float* __restrict__ blstm)
{
    extern __shared__ float s_dyn[];
    __shared__ unsigned s_tok[32];
    unsigned long long acc[2] = {0, 0};
    int bx = blockIdx.x;
    if (bx < 8) {
        int bcol = bx * 64;
        gemm_v4([&](int r, int k) { return g_h[p][r * HH + k]; },
                W1, HH, HH, HH, bcol, acc, s_dyn);
        store_tile(acc, g_hq, HH, bcol, HH, b1, 0);
    } else if (bx < 28) {
        int bcol = (bx - 8) * 64;
        gemm_v4([&](int r, int k) { return g_h[p][r * HH + k]; },
                Wg, FF, HH, FF, bcol, acc, s_dyn);
        store_tile(acc, g_gate, FF, bcol, FF, bg, 1);
    } else if (bx < 60) {
        if (threadIdx.x < 32)
            s_tok[threadIdx.x] =
                0xFFFFFFFFu - (unsigned)(g_amax[threadIdx.x] & 0xFFFFFFFFull);
        __syncthreads();
        int bcol = (bx - 28) * 64;
        gemm_v4([&](int r, int k) { return emb[(size_t)s_tok[r] * EE + k]; },
                Wx, G4, EE, G4, bcol, acc, s_dyn);
        store_tile(acc, g_gpart[0], G4, bcol, G4, blstm, 0);
    } else {
        int bcol = (bx - 60) * 64;
        gemm_v4([&](int r, int k) { return g_h[p][r * HH + k]; },
                Whh, G4, HH, G4, bcol, acc, s_dyn);
        store_tile(acc, g_gpart[1], G4, bcol, G4, nullptr, 0);
    }
}

// K_SCORE: raw Bahdanau scores (softmax shift-invariant -> bVa omitted).
// grid (B, 2) x 256 threads; 8 warps x 4 rows each.
__global__ void __launch_bounds__(256) k_score(const float* __restrict__ Va)
{
    __shared__ __align__(16) float s_hq[HH];
    __shared__ __align__(16) float s_va[HH];
    int b = blockIdx.x, half = blockIdx.y, tid = threadIdx.x;
    int w = tid >> 5, lane = tid & 31;
    for (int j = tid; j < HH; j += 256) { s_hq[j] = g_hq[b * HH + j]; s_va[j] = Va[j]; }
    __syncthreads();
#pragma unroll
    for (int q = 0; q < 4; q++) {
        int n = half * 32 + q * 8 + w;
        const float4* ep = (const float4*)(g_encproj + ((size_t)b * NN + n) * HH);
        float s = 0.f;
#pragma unroll
        for (int i = 0; i < 4; i++) {
            int e4 = lane + 32 * i;
            float4 v = ep[e4];
            float4 hq4 = *(const float4*)(s_hq + e4 * 4);
            float4 va4 = *(const float4*)(s_va + e4 * 4);
            s += fmaxf(v.x + hq4.x, 0.f) * va4.x;
            s += fmaxf(v.y + hq4.y, 0.f) * va4.y;
            s += fmaxf(v.z + hq4.z, 0.f) * va4.z;
            s += fmaxf(v.w + hq4.w, 0.f) * va4.w;
        }
#pragma unroll
        for (int m = 16; m; m >>= 1) s += __shfl_xor_sync(0xffffffffu, s, m);
        if (lane == 0) g_scor[b * NN + n] = s;
    }
}

// K_CTX: redundant softmax per block + gated context chunk. grid (B, 10) x 128.
__global__ void __launch_bounds__(128) k_ctx(int t, const float* __restrict__ feat,
                                             float* __restrict__ out)
{
    __shared__ float s_w[NN], s_red[4];
    int b = blockIdx.x, fc = blockIdx.y, tid = threadIdx.x;
    int lane = tid & 31;
    float v = 0.f;
    if (tid < 64) v = g_scor[b * NN + tid];
    float m = v;
#pragma unroll
    for (int s = 16; s; s >>= 1) m = fmaxf(m, __shfl_xor_sync(0xffffffffu, m, s));
    if (tid < 64 && lane == 0) s_red[tid >> 5] = m;
    __syncthreads();
    if (tid < 64) {
        float e = __expf(v - fmaxf(s_red[0], s_red[1]));
        s_w[tid] = e;
        float sum = e;
#pragma unroll
        for (int s = 16; s; s >>= 1) sum += __shfl_xor_sync(0xffffffffu, sum, s);
        if (lane == 0) s_red[2 + (tid >> 5)] = sum;
    }
    __syncthreads();
    float inv = 1.0f / (s_red[2] + s_red[3]);
    int f = fc * 128 + tid;
    const float* fb = feat + (size_t)b * NN * FF + f;
    float a = 0.f;
#pragma unroll 16
    for (int n = 0; n < NN; n++) a += s_w[n] * fb[(size_t)n * FF];
    a *= inv;
    g_ctxg[b * FF + f] = a * g_gate[b * FF + f];
    if (fc == 0 && tid < 64)
        out[OFF_ATT + ((size_t)b * TT + t) * NN + tid] = s_w[tid] * inv;
}

// K_G2: gpart[2+ks] = ctxg(kslice) @ WxBot(kslice)   (4 K-slices of 320)
__global__ void __launch_bounds__(512) k_g2(const float* __restrict__ Wx)
{
    extern __shared__ float s_dyn[];
    unsigned long long acc[2] = {0, 0};
    int ks = blockIdx.y;
    int bcol = blockIdx.x * 64;
    const float* Wp = Wx + (size_t)(EE + ks * 320) * G4;
    int koff = ks * 320;
    gemm_v4([&](int r, int k) { return g_ctxg[r * FF + koff + k]; },
            Wp, G4, 320, G4, bcol, acc, s_dyn);
    store_tile(acc, g_gpart[2 + ks], G4, bcol, G4, nullptr, 0);
}

// K_LSTM: sum 6 partials (fixed order), pointwise LSTM, write h/c. Reset argmax.
__global__ void __launch_bounds__(128) k_lstm(int p, int last, float* __restrict__ out)
{
    int b = blockIdx.x >> 2, ch = blockIdx.x & 3;
    int j = ch * 128 + threadIdx.x;
    float v[4];
#pragma unroll
    for (int g = 0; g < 4; g++) {
        float s = 0.f;
#pragma unroll
        for (int pt = 0; pt < 6; pt++) s += g_gpart[pt][b * G4 + g * HH + j];
        v[g] = s;
    }
    float c_old = g_c[p][b * HH + j];
    float c2 = sigf(v[1]) * c_old + sigf(v[0]) * tanhf(v[2]);
    float h2 = sigf(v[3]) * tanhf(c2);
    g_c[p ^ 1][b * HH + j] = c2;
    g_h[p ^ 1][b * HH + j] = h2;
    if (last) {
        out[OFF_H + b * HH + j] = h2;
        out[OFF_C + b * HH + j] = c2;
    }
    if (ch == 0 && threadIdx.x == 0) g_amax[b] = 0ull;
}

// K_OUT: logits = h2@Wout + bout; write dec out; packed-argmax per row.
__global__ void __launch_bounds__(512) k_out(int pn, int t,
                                             const float* __restrict__ Wout,
                                             const float* __restrict__ bout,
                                             float* __restrict__ out)
{
    extern __shared__ float s_dyn[];
    unsigned long long acc[2] = {0, 0};
    int bcol = blockIdx.x * 64;
    gemm_v4([&](int r, int k) { return g_h[pn][r * HH + k]; },
            Wout, VV, HH, VV, bcol, acc, s_dyn);
    int tid = threadIdx.x;
    int lane = tid & 31, rp = tid >> 5;
    int col0 = bcol + lane * 2;
    int r0 = 2 * rp, r1 = r0 + 1;
    float v0, v1, u0, u1;
    upk2(acc[0], v0, v1);
    upk2(acc[1], u0, u1);
    unsigned long long best0 = 0ull, best1 = 0ull;
#pragma unroll
    for (int q = 0; q < 2; q++) {
        int cc = col0 + q;
        if (cc < VV) {
            float lo = ((q == 0) ? v0 : v1) + bout[cc];
            float hi = ((q == 0) ? u0 : u1) + bout[cc];
            out[((size_t)r0 * TT + t) * VV + cc] = lo;
            out[((size_t)r1 * TT + t) * VV + cc] = hi;
            unsigned long long k0 =
                ((unsigned long long)mono32(lo) << 32) | (0xFFFFFFFFu - (unsigned)cc);
            unsigned long long k1 =
                ((unsigned long long)mono32(hi) << 32) | (0xFFFFFFFFu - (unsigned)cc);
            if (k0 > best0) best0 = k0;
            if (k1 > best1) best1 = k1;
        }
    }
#pragma unroll
    for (int m = 16; m; m >>= 1) {
        unsigned long long o0 = __shfl_xor_sync(0xffffffffu, best0, m);
        unsigned long long o1 = __shfl_xor_sync(0xffffffffu, best1, m);
        if (o0 > best0) best0 = o0;
        if (o1 > best1) best1 = o1;
    }
    if (lane == 0) {
        atomicMax(&g_amax[r0], best0);
        atomicMax(&g_amax[r1], best1);
    }
}

// ---------------- launch ----------------
extern "C" void kernel_launch(void* const* d_in, const int* in_sizes, int n_in,
                              void* d_out, int out_size)
{
    int off = (n_in >= 21) ? 1 : 0;
    const float* feat  = (const float*)d_in[0];
    const float* emb   = (const float*)d_in[2 + off];
    const float* W1    = (const float*)d_in[3 + off];
    const float* b1    = (const float*)d_in[4 + off];
    const float* W2    = (const float*)d_in[5 + off];
    const float* b2    = (const float*)d_in[6 + off];
    const float* Va    = (const float*)d_in[7 + off];
    const float* Wh    = (const float*)d_in[9 + off];
    const float* bh    = (const float*)d_in[10 + off];
    const float* Wc    = (const float*)d_in[11 + off];
    const float* bc    = (const float*)d_in[12 + off];
    const float* Wg    = (const float*)d_in[13 + off];
    const float* bg    = (const float*)d_in[14 + off];
    const float* Wx    = (const float*)d_in[15 + off];
    const float* Whh   = (const float*)d_in[16 + off];
    const float* blstm = (const float*)d_in[17 + off];
    const float* Wout  = (const float*)d_in[18 + off];
    const float* bout  = (const float*)d_in[19 + off];
    float* out = (float*)d_out;

    const int SM512  = 32 * 512 * 4;    // 65536
    const int SM320  = 32 * 320 * 4;    // 40960
    const int SM1280 = 32 * 1280 * 4;   // 163840
    cudaFuncSetAttribute(k_g1, cudaFuncAttributeMaxDynamicSharedMemorySize, SM512);
    cudaFuncSetAttribute(k_g2, cudaFuncAttributeMaxDynamicSharedMemorySize, SM320);
    cudaFuncSetAttribute(k_out, cudaFuncAttributeMaxDynamicSharedMemorySize, SM512);
    cudaFuncSetAttribute(k_encproj, cudaFuncAttributeMaxDynamicSharedMemorySize, SM1280);

    k_init<<<BB, 256>>>(feat, Wh, bh, Wc, bc);
    k_encproj<<<dim3(HH / 64, (BB * NN) / 32), 512, SM1280>>>(feat, W2, b2);

    for (int t = 0; t < TT; t++) {
        int p = t & 1;
        k_g1<<<92, 512, SM512>>>(p, emb, W1, b1, Wg, bg, Wx, Whh, blstm);
        k_score<<<dim3(BB, 2), 256>>>(Va);
        k_ctx<<<dim3(BB, 10), 128>>>(t, feat, out);
        k_g2<<<dim3(G4 / 64, 4), 512, SM320>>>(Wx);
        k_lstm<<<BB * 4, 128>>>(p, (t == TT - 1) ? 1 : 0, out);
        k_out<<<(VV + 63) / 64, 512, SM512>>>(p ^ 1, t, Wout, bout, out);
    }
}

// round 5
// speedup vs baseline: 1.3314x; 1.3314x over previous
#include <cuda_runtime.h>
#include <cuda_bf16.h>
#include <cstdint>

#define BB 32
#define NN 64
#define FF 1280
#define HH 512
#define EE 512
#define VV 10000
#define TT 80
#define G4 2048

#define OFF_H   25600000ll
#define OFF_C   25616384ll
#define OFF_ATT 25632768ll

// ---------------- device state ----------------
__device__ float g_h[2][BB * HH];
__device__ float g_c[2][BB * HH];
__device__ float g_hq[BB * HH];
__device__ float g_gate[BB * FF];
__device__ float g_ctxg[BB * FF];
__device__ float g_scor[BB * NN];
__device__ float g_encproj[BB * NN * HH];
__device__ float g_gpart[6][BB * G4];
__device__ unsigned long long g_amax[BB];

// ---------------- helpers ----------------
__device__ __forceinline__ unsigned long long pk2(float lo, float hi) {
    unsigned long long r;
    asm("mov.b64 %0, {%1,%2};" : "=l"(r) : "f"(lo), "f"(hi));
    return r;
}
__device__ __forceinline__ void upk2(unsigned long long v, float& lo, float& hi) {
    asm("mov.b64 {%0,%1}, %2;" : "=f"(lo), "=f"(hi) : "l"(v));
}
__device__ __forceinline__ void fma2(unsigned long long& d, unsigned long long a,
                                     unsigned long long b) {
    asm("fma.rn.f32x2 %0, %1, %2, %0;" : "+l"(d) : "l"(a), "l"(b));
}
__device__ __forceinline__ float sigf(float x) { return 1.0f / (1.0f + expf(-x)); }
__device__ __forceinline__ unsigned mono32(float f) {
    unsigned u = __float_as_uint(f);
    return (u & 0x80000000u) ? ~u : (u | 0x80000000u);
}
__device__ __forceinline__ uint32_t s2u(const void* p) {
    return (uint32_t)__cvta_generic_to_shared(p);
}
__device__ __forceinline__ void cp16(uint32_t dst, const void* src) {
    asm volatile("cp.async.ca.shared.global [%0], [%1], 16;" :: "r"(dst), "l"(src));
}
__device__ __forceinline__ void cp_commit() {
    asm volatile("cp.async.commit_group;");
}
template <int n>
__device__ __forceinline__ void cp_wait() {
    asm volatile("cp.async.wait_group %0;" :: "n"(n));
}

// ---------------- GEMM v5 ----------------
// C[32, 64-col tile] = A[32,K] @ W[K,N].  256 threads (8 warps).
// warp w -> rows 4w..4w+3 ; lane -> cols (col0, col0+1), col0 = bcol + 2*lane.
// A staged once into smem as s_a[k*34 + row]  (broadcast LDS.64 reads).
// W streamed via cp.async, double-buffered 64-k chunks (16KB each).
#define CHK 64
#define WBUF (CHK * 64)      // floats per W buffer

__device__ __forceinline__ void fill_w(const float* __restrict__ W, int ldw,
                                       int bcol, int N, int k0, float* s_wbuf)
{
    int tid = threadIdx.x;
    int kk = tid >> 4;             // 0..15
    int c4 = (tid & 15) * 4;       // 0..60
    int col = bcol + c4;
#pragma unroll
    for (int p = 0; p < 4; p++) {
        int k = k0 + kk + p * 16;
        if (col < N)
            cp16(s2u(s_wbuf + (kk + p * 16) * 64 + c4),
                 W + (size_t)k * ldw + col);
    }
    cp_commit();
}

template <int K, class AElem>
__device__ __forceinline__ void gemm_v5(AElem aelem, const float* __restrict__ W,
    int ldw, int N, int bcol, unsigned long long acc[4], float* s_dyn)
{
    const int tid = threadIdx.x;
    const int lane = tid & 31;
    const int w = tid >> 5;
    float* s_w = s_dyn;                  // 2 * WBUF floats
    float* s_a = s_dyn + 2 * WBUF;       // K*34 floats
    constexpr int C = K / CHK;

    fill_w(W, ldw, bcol, N, 0, s_w);
    if (C > 1) fill_w(W, ldw, bcol, N, CHK, s_w + WBUF);

    // stage A: s_a[k*34 + r]
#pragma unroll 1
    for (int r = 0; r < 32; r++) {
#pragma unroll
        for (int k = 0; k < K / 256; k++)
            s_a[(k * 256 + tid) * 34 + r] = aelem(r, k * 256 + tid);
        if (K % 256) {
            int k = (K / 256) * 256 + tid;
            if (k < K) s_a[k * 34 + r] = aelem(r, k);
        }
    }

    const float* sa = s_a + 4 * w;
#pragma unroll 1
    for (int c = 0; c < C; c++) {
        if (c + 1 < C) cp_wait<1>(); else cp_wait<0>();
        __syncthreads();
        const float* sw = s_w + (c & 1) * WBUF + 2 * lane;
        const float* sac = sa + c * CHK * 34;
#pragma unroll 16
        for (int kk = 0; kk < CHK; kk++) {
            float2 w2 = *(const float2*)(sw + kk * 64);
            float2 a01 = *(const float2*)(sac + kk * 34);
            float2 a23 = *(const float2*)(sac + kk * 34 + 2);
            unsigned long long wp = pk2(w2.x, w2.y);
            fma2(acc[0], wp, pk2(a01.x, a01.x));
            fma2(acc[1], wp, pk2(a01.y, a01.y));
            fma2(acc[2], wp, pk2(a23.x, a23.x));
            fma2(acc[3], wp, pk2(a23.y, a23.y));
        }
        if (c + 2 < C) {
            __syncthreads();
            fill_w(W, ldw, bcol, N, (c + 2) * CHK, s_w + (c & 1) * WBUF);
        }
    }
}

// Epilogue: +bias, optional sigmoid, store (with N guard).
__device__ __forceinline__ void store_tile(unsigned long long acc[4],
    float* C, int ldc, int bcol, int N, const float* __restrict__ bias, int act)
{
    int lane = threadIdx.x & 31, w = threadIdx.x >> 5;
    int col0 = bcol + lane * 2;
    float b0 = 0.f, b1 = 0.f;
    if (bias) {
        if (col0 < N) b0 = bias[col0];
        if (col0 + 1 < N) b1 = bias[col0 + 1];
    }
#pragma unroll
    for (int r = 0; r < 4; r++) {
        int row = 4 * w + r;
        float a, b;
        upk2(acc[r], a, b);
        a += b0; b += b1;
        if (act == 1) { a = sigf(a); b = sigf(b); }
        if (col0 < N)     C[(size_t)row * ldc + col0] = a;
        if (col0 + 1 < N) C[(size_t)row * ldc + col0 + 1] = b;
    }
}

// ---------------- setup ----------------
__global__ void __launch_bounds__(256) k_encproj(const float* __restrict__ feat,
                                                 const float* __restrict__ W2,
                                                 const float* __restrict__ b2)
{
    extern __shared__ float s_dyn[];
    unsigned long long acc[4] = {0, 0, 0, 0};
    int bcol = blockIdx.x * 64;
    const float* A = feat + (size_t)blockIdx.y * 32 * FF;
    gemm_v5<FF>([&](int r, int k) { return A[(size_t)r * FF + k]; },
                W2, HH, HH, bcol, acc, s_dyn);
    store_tile(acc, g_encproj + (size_t)blockIdx.y * 32 * HH, HH, bcol, HH, b2, 0);
}

__global__ void __launch_bounds__(256) k_init(const float* __restrict__ feat,
                                              const float* __restrict__ Wh,
                                              const float* __restrict__ bh,
                                              const float* __restrict__ Wc,
                                              const float* __restrict__ bc)
{
    __shared__ float s_mean[FF];
    int b = blockIdx.x, tid = threadIdx.x;
    const float* fb = feat + (size_t)b * NN * FF;
    for (int f = tid; f < FF; f += 256) {
        float s = 0.f;
#pragma unroll 8
        for (int n = 0; n < NN; n++) s += fb[(size_t)n * FF + f];
        s_mean[f] = s * (1.0f / NN);
    }
    __syncthreads();
    for (int j = tid; j < HH; j += 256) {
        float ha = bh[j], ca = bc[j];
#pragma unroll 8
        for (int f = 0; f < FF; f++) {
            float m = s_mean[f];
            ha = fmaf(m, Wh[(size_t)f * HH + j], ha);
            ca = fmaf(m, Wc[(size_t)f * HH + j], ca);
        }
        g_h[0][b * HH + j] = ha;
        g_c[0][b * HH + j] = ca;
    }
    if (tid == 0) g_amax[b] = (unsigned long long)(0xFFFFFFFFu - 1u);  // SOS=1
}

// ---------------- per-step ----------------
// K_G1: hq = h@W1+b1 ; gate = sig(h@Wg+bg) ; gpart0 = emb[tok]@WxTop+blstm ; gpart1 = h@Whh
__global__ void __launch_bounds__(256) k_g1(int p, const float* __restrict__ emb,
    const float* __restrict__ W1, const float* __restrict__ b1,
    const float* __restrict__ Wg, const float* __restrict__ bg,
    const float* __restrict__ Wx, const float* __restrict__ Whh,
    const float* __restrict__ blstm)
{
    extern __shared__ float s_dyn[];
    __shared__ unsigned s_tok[32];
    unsigned long long acc[4] = {0, 0, 0, 0};
    int bx = blockIdx.x;
    if (bx < 8) {
        int bcol = bx * 64;
        gemm_v5<HH>([&](int r, int k) { return g_h[p][r * HH + k]; },
                    W1, HH, HH, bcol, acc, s_dyn);
        store_tile(acc, g_hq, HH, bcol, HH, b1, 0);
    } else if (bx < 28) {
        int bcol = (bx - 8) * 64;
        gemm_v5<HH>([&](int r, int k) { return g_h[p][r * HH + k]; },
                    Wg, FF, FF, bcol, acc, s_dyn);
        store_tile(acc, g_gate, FF, bcol, FF, bg, 1);
    } else if (bx < 60) {
        if (threadIdx.x < 32)
            s_tok[threadIdx.x] =
                0xFFFFFFFFu - (unsigned)(g_amax[threadIdx.x] & 0xFFFFFFFFull);
        __syncthreads();
        int bcol = (bx - 28) * 64;
        gemm_v5<EE>([&](int r, int k) { return emb[(size_t)s_tok[r] * EE + k]; },
                    Wx, G4, G4, bcol, acc, s_dyn);
        store_tile(acc, g_gpart[0], G4, bcol, G4, blstm, 0);
    } else {
        int bcol = (bx - 60) * 64;
        gemm_v5<HH>([&](int r, int k) { return g_h[p][r * HH + k]; },
                    Whh, G4, G4, bcol, acc, s_dyn);
        store_tile(acc, g_gpart[1], G4, bcol, G4, nullptr, 0);
    }
}

// K_SCORE: raw Bahdanau scores. grid (B, 8) x 256; one row per warp.
__global__ void __launch_bounds__(256) k_score(const float* __restrict__ Va)
{
    __shared__ __align__(16) float s_hq[HH];
    __shared__ __align__(16) float s_va[HH];
    int b = blockIdx.x, tid = threadIdx.x;
    int w = tid >> 5, lane = tid & 31;
    for (int j = tid; j < HH; j += 256) { s_hq[j] = g_hq[b * HH + j]; s_va[j] = Va[j]; }
    __syncthreads();
    int n = blockIdx.y * 8 + w;
    const float4* ep = (const float4*)(g_encproj + ((size_t)b * NN + n) * HH);
    float s = 0.f;
#pragma unroll
    for (int i = 0; i < 4; i++) {
        int e4 = lane + 32 * i;
        float4 v = ep[e4];
        float4 hq4 = *(const float4*)(s_hq + e4 * 4);
        float4 va4 = *(const float4*)(s_va + e4 * 4);
        s += fmaxf(v.x + hq4.x, 0.f) * va4.x;
        s += fmaxf(v.y + hq4.y, 0.f) * va4.y;
        s += fmaxf(v.z + hq4.z, 0.f) * va4.z;
        s += fmaxf(v.w + hq4.w, 0.f) * va4.w;
    }
#pragma unroll
    for (int m = 16; m; m >>= 1) s += __shfl_xor_sync(0xffffffffu, s, m);
    if (lane == 0) g_scor[b * NN + n] = s;
}

// K_CTX: redundant softmax per block + gated context chunk. grid (B, 10) x 128.
__global__ void __launch_bounds__(128) k_ctx(int t, const float* __restrict__ feat,
                                             float* __restrict__ out)
{
    __shared__ float s_w[NN], s_red[4];
    int b = blockIdx.x, fc = blockIdx.y, tid = threadIdx.x;
    int lane = tid & 31;
    float v = 0.f;
    if (tid < 64) v = g_scor[b * NN + tid];
    float m = v;
#pragma unroll
    for (int s = 16; s; s >>= 1) m = fmaxf(m, __shfl_xor_sync(0xffffffffu, m, s));
    if (tid < 64 && lane == 0) s_red[tid >> 5] = m;
    __syncthreads();
    if (tid < 64) {
        float e = __expf(v - fmaxf(s_red[0], s_red[1]));
        s_w[tid] = e;
        float sum = e;
#pragma unroll
        for (int s = 16; s; s >>= 1) sum += __shfl_xor_sync(0xffffffffu, sum, s);
        if (lane == 0) s_red[2 + (tid >> 5)] = sum;
    }
    __syncthreads();
    float inv = 1.0f / (s_red[2] + s_red[3]);
    int f = fc * 128 + tid;
    const float* fb = feat + (size_t)b * NN * FF + f;
    float a = 0.f;
#pragma unroll 16
    for (int n = 0; n < NN; n++) a += s_w[n] * fb[(size_t)n * FF];
    a *= inv;
    g_ctxg[b * FF + f] = a * g_gate[b * FF + f];
    if (fc == 0 && tid < 64)
        out[OFF_ATT + ((size_t)b * TT + t) * NN + tid] = s_w[tid] * inv;
}

// K_G2: gpart[2+ks] = ctxg(kslice) @ WxBot(kslice)   (4 K-slices of 320)
__global__ void __launch_bounds__(256) k_g2(const float* __restrict__ Wx)
{
    extern __shared__ float s_dyn[];
    unsigned long long acc[4] = {0, 0, 0, 0};
    int ks = blockIdx.y;
    int bcol = blockIdx.x * 64;
    const float* Wp = Wx + (size_t)(EE + ks * 320) * G4;
    int koff = ks * 320;
    gemm_v5<320>([&](int r, int k) { return g_ctxg[r * FF + koff + k]; },
                 Wp, G4, G4, bcol, acc, s_dyn);
    store_tile(acc, g_gpart[2 + ks], G4, bcol, G4, nullptr, 0);
}

// K_LSTM: sum 6 partials (fixed order), pointwise LSTM, write h/c. Reset argmax.
__global__ void __launch_bounds__(128) k_lstm(int p, int last, float* __restrict__ out)
{
    int b = blockIdx.x >> 2, ch = blockIdx.x & 3;
    int j = ch * 128 + threadIdx.x;
    float v[4];
#pragma unroll
    for (int g = 0; g < 4; g++) {
        float s = 0.f;
#pragma unroll
        for (int pt = 0; pt < 6; pt++) s += g_gpart[pt][b * G4 + g * HH + j];
        v[g] = s;
    }
    float c_old = g_c[p][b * HH + j];
    float c2 = sigf(v[1]) * c_old + sigf(v[0]) * tanhf(v[2]);
    float h2 = sigf(v[3]) * tanhf(c2);
    g_c[p ^ 1][b * HH + j] = c2;
    g_h[p ^ 1][b * HH + j] = h2;
    if (last) {
        out[OFF_H + b * HH + j] = h2;
        out[OFF_C + b * HH + j] = c2;
    }
    if (ch == 0 && threadIdx.x == 0) g_amax[b] = 0ull;
}

// K_OUT: logits = h2@Wout + bout; write dec out; packed-argmax per row.
__global__ void __launch_bounds__(256) k_out(int pn, int t,
                                             const float* __restrict__ Wout,
                                             const float* __restrict__ bout,
                                             float* __restrict__ out)
{
    extern __shared__ float s_dyn[];
    unsigned long long acc[4] = {0, 0, 0, 0};
    int bcol = blockIdx.x * 64;
    gemm_v5<HH>([&](int r, int k) { return g_h[pn][r * HH + k]; },
                Wout, VV, VV, bcol, acc, s_dyn);
    int tid = threadIdx.x;
    int lane = tid & 31, w = tid >> 5;
    int col0 = bcol + lane * 2;
    float b0 = (col0 < VV) ? bout[col0] : 0.f;
    float b1 = (col0 + 1 < VV) ? bout[col0 + 1] : 0.f;
#pragma unroll
    for (int r = 0; r < 4; r++) {
        int row = 4 * w + r;
        float a, b;
        upk2(acc[r], a, b);
        a += b0; b += b1;
        unsigned long long best = 0ull;
        if (col0 < VV) {
            out[((size_t)row * TT + t) * VV + col0] = a;
            best = ((unsigned long long)mono32(a) << 32) | (0xFFFFFFFFu - (unsigned)col0);
        }
        if (col0 + 1 < VV) {
            out[((size_t)row * TT + t) * VV + col0 + 1] = b;
            unsigned long long k1 = ((unsigned long long)mono32(b) << 32) |
                                    (0xFFFFFFFFu - (unsigned)(col0 + 1));
            if (k1 > best) best = k1;
        }
#pragma unroll
        for (int m = 16; m; m >>= 1) {
            unsigned long long o = __shfl_xor_sync(0xffffffffu, best, m);
            if (o > best) best = o;
        }
        if (lane == 0) atomicMax(&g_amax[row], best);
    }
}

// ---------------- launch ----------------
extern "C" void kernel_launch(void* const* d_in, const int* in_sizes, int n_in,
                              void* d_out, int out_size)
{
    int off = (n_in >= 21) ? 1 : 0;
    const float* feat  = (const float*)d_in[0];
    const float* emb   = (const float*)d_in[2 + off];
    const float* W1    = (const float*)d_in[3 + off];
    const float* b1    = (const float*)d_in[4 + off];
    const float* W2    = (const float*)d_in[5 + off];
    const float* b2    = (const float*)d_in[6 + off];
    const float* Va    = (const float*)d_in[7 + off];
    const float* Wh    = (const float*)d_in[9 + off];
    const float* bh    = (const float*)d_in[10 + off];
    const float* Wc    = (const float*)d_in[11 + off];
    const float* bc    = (const float*)d_in[12 + off];
    const float* Wg    = (const float*)d_in[13 + off];
    const float* bg    = (const float*)d_in[14 + off];
    const float* Wx    = (const float*)d_in[15 + off];
    const float* Whh   = (const float*)d_in[16 + off];
    const float* blstm = (const float*)d_in[17 + off];
    const float* Wout  = (const float*)d_in[18 + off];
    const float* bout  = (const float*)d_in[19 + off];
    float* out = (float*)d_out;

    const int SMW   = 2 * WBUF * 4;                 // 32768
    const int SM512 = SMW + HH * 34 * 4;            // 102400
    const int SM320 = SMW + 320 * 34 * 4;           // 76288
    const int SM1280 = SMW + FF * 34 * 4;           // 206848
    cudaFuncSetAttribute(k_g1, cudaFuncAttributeMaxDynamicSharedMemorySize, SM512);
    cudaFuncSetAttribute(k_g2, cudaFuncAttributeMaxDynamicSharedMemorySize, SM320);
    cudaFuncSetAttribute(k_out, cudaFuncAttributeMaxDynamicSharedMemorySize, SM512);
    cudaFuncSetAttribute(k_encproj, cudaFuncAttributeMaxDynamicSharedMemorySize, SM1280);

    k_init<<<BB, 256>>>(feat, Wh, bh, Wc, bc);
    k_encproj<<<dim3(HH / 64, (BB * NN) / 32), 256, SM1280>>>(feat, W2, b2);

    for (int t = 0; t < TT; t++) {
        int p = t & 1;
        k_g1<<<92, 256, SM512>>>(p, emb, W1, b1, Wg, bg, Wx, Whh, blstm);
        k_score<<<dim3(BB, 8), 256>>>(Va);
        k_ctx<<<dim3(BB, 10), 128>>>(t, feat, out);
        k_g2<<<dim3(G4 / 64, 4), 256, SM320>>>(Wx);
        k_lstm<<<BB * 4, 128>>>(p, (t == TT - 1) ? 1 : 0, out);
        k_out<<<(VV + 63) / 64, 256, SM512>>>(p ^ 1, t, Wout, bout, out);
    }
}